// round 3
// baseline (speedup 1.0000x reference)
#include <cuda_runtime.h>
#include <math.h>

#define NB 8
#define CC 1024
#define WW 1024
#define HH 16
#define DD 64

// Scratch for Q, K, V projections, each [N, C, W] fp32 (32 MB each).
__device__ float g_q[NB * CC * WW];
__device__ float g_k[NB * CC * WW];
__device__ float g_v[NB * CC * WW];

// ---------------------------------------------------------------------------
// Kernel 1: fused QKV projection.
// For each batch n and proj p in {q,k,v}:  Out[o][w] = sum_c Wm[o][c]*Hid[c][w] + b[o]
// Classic 128x128x16 SGEMM tile, 256 threads, 8x8 register tiles with
// split-half (tx*4 / 64+tx*4) column mapping for conflict-free LDS.128.
// ---------------------------------------------------------------------------
__global__ __launch_bounds__(256, 2) void qkv_kernel(
    const float* __restrict__ hid,
    const float* __restrict__ wq, const float* __restrict__ bq,
    const float* __restrict__ wk, const float* __restrict__ bk,
    const float* __restrict__ wv, const float* __restrict__ bv)
{
    const int z = blockIdx.z;
    const int n = z / 3;
    const int p = z - 3 * n;

    const float* __restrict__ A;
    const float* __restrict__ bias;
    float* __restrict__ out;
    if (p == 0)      { A = wq; bias = bq; out = g_q; }
    else if (p == 1) { A = wk; bias = bk; out = g_k; }
    else             { A = wv; bias = bv; out = g_v; }

    const float* __restrict__ B = hid + (size_t)n * CC * WW;
    out += (size_t)n * CC * WW;

    const int m0 = blockIdx.y * 128;
    const int w0 = blockIdx.x * 128;

    __shared__ float As[16][128];
    __shared__ float Bs[16][128];

    const int tid = threadIdx.x;
    const int tx = tid % 16;
    const int ty = tid / 16;

    float acc[8][8];
#pragma unroll
    for (int i = 0; i < 8; i++)
#pragma unroll
        for (int j = 0; j < 8; j++) acc[i][j] = 0.0f;

    // A-load mapping: lane-contiguous m (conflict-free smem stores)
    const int am  = tid % 128;   // m row
    const int ak4 = tid / 128;   // 0..1 -> k float4 index {ak4, ak4+2}
    // B-load mapping
    const int br  = tid / 32;    // k row 0..7 (also +8)
    const int bc4 = tid % 32;    // w float4 col

    for (int kt = 0; kt < CC; kt += 16) {
        // Load A tile (weights, L2-hot): 128m x 16k
        float4 a0 = *(const float4*)&A[(size_t)(m0 + am) * CC + kt + ak4 * 4];
        float4 a1 = *(const float4*)&A[(size_t)(m0 + am) * CC + kt + (ak4 + 2) * 4];
        As[ak4 * 4 + 0][am] = a0.x; As[ak4 * 4 + 1][am] = a0.y;
        As[ak4 * 4 + 2][am] = a0.z; As[ak4 * 4 + 3][am] = a0.w;
        As[(ak4 + 2) * 4 + 0][am] = a1.x; As[(ak4 + 2) * 4 + 1][am] = a1.y;
        As[(ak4 + 2) * 4 + 2][am] = a1.z; As[(ak4 + 2) * 4 + 3][am] = a1.w;

        // Load B tile (activations): 16k x 128w, fully coalesced
        float4 b0 = *(const float4*)&B[(size_t)(kt + br) * WW + w0 + bc4 * 4];
        float4 b1 = *(const float4*)&B[(size_t)(kt + br + 8) * WW + w0 + bc4 * 4];
        *(float4*)&Bs[br][bc4 * 4]     = b0;
        *(float4*)&Bs[br + 8][bc4 * 4] = b1;

        __syncthreads();

#pragma unroll
        for (int k = 0; k < 16; k++) {
            float4 alo = *(const float4*)&As[k][ty * 4];
            float4 ahi = *(const float4*)&As[k][64 + ty * 4];
            float4 blo = *(const float4*)&Bs[k][tx * 4];
            float4 bhi = *(const float4*)&Bs[k][64 + tx * 4];
            float ar[8] = {alo.x, alo.y, alo.z, alo.w, ahi.x, ahi.y, ahi.z, ahi.w};
            float br_[8] = {blo.x, blo.y, blo.z, blo.w, bhi.x, bhi.y, bhi.z, bhi.w};
#pragma unroll
            for (int i = 0; i < 8; i++)
#pragma unroll
                for (int j = 0; j < 8; j++) acc[i][j] += ar[i] * br_[j];
        }
        __syncthreads();
    }

    // Epilogue: bias + store
#pragma unroll
    for (int i = 0; i < 8; i++) {
        int m = (i < 4) ? (m0 + ty * 4 + i) : (m0 + 64 + ty * 4 + (i - 4));
        float bv_ = bias[m];
        float4 olo = {acc[i][0] + bv_, acc[i][1] + bv_, acc[i][2] + bv_, acc[i][3] + bv_};
        float4 ohi = {acc[i][4] + bv_, acc[i][5] + bv_, acc[i][6] + bv_, acc[i][7] + bv_};
        *(float4*)&out[(size_t)m * WW + w0 + tx * 4]      = olo;
        *(float4*)&out[(size_t)m * WW + w0 + 64 + tx * 4] = ohi;
    }
}

// ---------------------------------------------------------------------------
// Kernel 2: flash attention per (n, h, 64-query tile).
// Q,K,V scratch layout: [n][h*64+d][w].  S[q][k] = sum_d Q[d][q]K[d][k] / 8 + mask[k]
// Online softmax in registers; P staged in smem (aliased over K tile);
// V transposed at load for conflict-free P@V.
// Output: out[n][h*64+d][q] = ctx[q][d].
// ---------------------------------------------------------------------------
__global__ __launch_bounds__(256) void attn_kernel(
    const float* __restrict__ mask, float* __restrict__ out)
{
    const int qb = blockIdx.x;           // 0..15
    const int nh = blockIdx.y;           // 0..127
    const int n  = nh / HH;
    const int h  = nh - n * HH;
    const int q0 = qb * 64;

    const float* __restrict__ Qg = g_q + ((size_t)n * CC + h * DD) * WW;
    const float* __restrict__ Kg = g_k + ((size_t)n * CC + h * DD) * WW;
    const float* __restrict__ Vg = g_v + ((size_t)n * CC + h * DD) * WW;

    __shared__ float Qs[64][64];     // [d][q]
    __shared__ float KP[64][64];     // K tile [d][k], reused as P tile [q][k]
    __shared__ float Vt[64][64];     // V transposed [k][d]

    const int tid = threadIdx.x;
    const int tx  = tid % 16;
    const int ty  = tid / 16;

    // Load Q tile: [d][q], coalesced float4 along q
    {
        const int c4 = tid % 16;
        const int r  = tid / 16;
#pragma unroll
        for (int it = 0; it < 4; it++) {
            int d = r + it * 16;
            *(float4*)&Qs[d][c4 * 4] =
                *(const float4*)&Qg[(size_t)d * WW + q0 + c4 * 4];
        }
    }

    float m_i[4], l_i[4], O[4][4];
#pragma unroll
    for (int i = 0; i < 4; i++) {
        m_i[i] = -INFINITY; l_i[i] = 0.0f;
#pragma unroll
        for (int j = 0; j < 4; j++) O[i][j] = 0.0f;
    }

    const int vd  = tid % 64;    // V-load: d row (lane-contiguous -> cf stores)
    const int vk0 = tid / 64;    // base k float4 index

    for (int k0 = 0; k0 < WW; k0 += 64) {
        // Load K tile [d][k]
        {
            const int c4 = tid % 16;
            const int r  = tid / 16;
#pragma unroll
            for (int it = 0; it < 4; it++) {
                int d = r + it * 16;
                *(float4*)&KP[d][c4 * 4] =
                    *(const float4*)&Kg[(size_t)d * WW + k0 + c4 * 4];
            }
        }
        // Load V tile transposed -> Vt[k][d]
#pragma unroll
        for (int it = 0; it < 4; it++) {
            int kk = vk0 + it * 4;   // float4 index along k
            float4 vv = *(const float4*)&Vg[(size_t)vd * WW + k0 + kk * 4];
            Vt[kk * 4 + 0][vd] = vv.x;
            Vt[kk * 4 + 1][vd] = vv.y;
            Vt[kk * 4 + 2][vd] = vv.z;
            Vt[kk * 4 + 3][vd] = vv.w;
        }
        __syncthreads();

        // S = Q^T K for this tile (4q x 4k per thread)
        float s[4][4];
#pragma unroll
        for (int i = 0; i < 4; i++)
#pragma unroll
            for (int j = 0; j < 4; j++) s[i][j] = 0.0f;

#pragma unroll
        for (int d = 0; d < 64; d++) {
            float4 qa = *(const float4*)&Qs[d][ty * 4];
            float4 kb = *(const float4*)&KP[d][tx * 4];
            float qr[4] = {qa.x, qa.y, qa.z, qa.w};
            float kr[4] = {kb.x, kb.y, kb.z, kb.w};
#pragma unroll
            for (int i = 0; i < 4; i++)
#pragma unroll
                for (int j = 0; j < 4; j++) s[i][j] += qr[i] * kr[j];
        }

        // scale + mask
        float mk[4];
#pragma unroll
        for (int j = 0; j < 4; j++) mk[j] = mask[(size_t)n * WW + k0 + tx * 4 + j];
#pragma unroll
        for (int i = 0; i < 4; i++)
#pragma unroll
            for (int j = 0; j < 4; j++) s[i][j] = s[i][j] * 0.125f + mk[j];

        // online softmax update (row stats across the 16 tx lanes)
        float pr[4][4];
#pragma unroll
        for (int i = 0; i < 4; i++) {
            float tmax = fmaxf(fmaxf(s[i][0], s[i][1]), fmaxf(s[i][2], s[i][3]));
#pragma unroll
            for (int off = 8; off >= 1; off >>= 1)
                tmax = fmaxf(tmax, __shfl_xor_sync(0xffffffffu, tmax, off));
            float newm = fmaxf(m_i[i], tmax);
            float corr = __expf(m_i[i] - newm);
            float rsum = 0.0f;
#pragma unroll
            for (int j = 0; j < 4; j++) {
                pr[i][j] = __expf(s[i][j] - newm);
                rsum += pr[i][j];
            }
#pragma unroll
            for (int off = 8; off >= 1; off >>= 1)
                rsum += __shfl_xor_sync(0xffffffffu, rsum, off);
            l_i[i] = l_i[i] * corr + rsum;
            m_i[i] = newm;
#pragma unroll
            for (int j = 0; j < 4; j++) O[i][j] *= corr;
        }

        __syncthreads();   // done reading K -> safe to overwrite as P

        // Stage P in smem: KP reused as Ps[q][k]
#pragma unroll
        for (int i = 0; i < 4; i++) {
            float4 pv = {pr[i][0], pr[i][1], pr[i][2], pr[i][3]};
            *(float4*)&KP[ty * 4 + i][tx * 4] = pv;
        }
        __syncthreads();

        // O += P @ V^T   (thread owns 4q x 4d)
#pragma unroll
        for (int k = 0; k < 64; k++) {
            float pa[4];
#pragma unroll
            for (int i = 0; i < 4; i++) pa[i] = KP[ty * 4 + i][k];
            float4 vb = *(const float4*)&Vt[k][tx * 4];
            float vr[4] = {vb.x, vb.y, vb.z, vb.w};
#pragma unroll
            for (int i = 0; i < 4; i++)
#pragma unroll
                for (int j = 0; j < 4; j++) O[i][j] += pa[i] * vr[j];
        }
        __syncthreads();   // before next tile overwrites KP / Vt
    }

    // Normalize and write: out[n][h*64+d][q0+q], contiguous in q -> float4 over i
#pragma unroll
    for (int i = 0; i < 4; i++) {
        float inv = 1.0f / l_i[i];
#pragma unroll
        for (int j = 0; j < 4; j++) O[i][j] *= inv;
    }
#pragma unroll
    for (int j = 0; j < 4; j++) {
        int d = tx * 4 + j;
        float4 o4 = {O[0][j], O[1][j], O[2][j], O[3][j]};
        *(float4*)&out[((size_t)n * CC + h * DD + d) * WW + q0 + ty * 4] = o4;
    }
}

// ---------------------------------------------------------------------------
extern "C" void kernel_launch(void* const* d_in, const int* in_sizes, int n_in,
                              void* d_out, int out_size)
{
    const float* hid  = (const float*)d_in[0];
    const float* mask = (const float*)d_in[1];
    const float* wq   = (const float*)d_in[2];
    const float* bq   = (const float*)d_in[3];
    const float* wk   = (const float*)d_in[4];
    const float* bk   = (const float*)d_in[5];
    const float* wv   = (const float*)d_in[6];
    const float* bv   = (const float*)d_in[7];
    float* out = (float*)d_out;

    dim3 g1(WW / 128, CC / 128, NB * 3);   // (8, 8, 24)
    qkv_kernel<<<g1, 256>>>(hid, wq, bq, wk, bk, wv, bv);

    dim3 g2(WW / 64, NB * HH);             // (16, 128)
    attn_kernel<<<g2, 256>>>(mask, out);
}